// round 3
// baseline (speedup 1.0000x reference)
#include <cuda_runtime.h>

#define NN 50000
#define EE 800000
#define DH 128
#define DE 16
#define LLAY 3
#define NBLK 49   // ceil(NN/1024)

typedef unsigned long long u64;

// ---------- packed f32x2 helpers (sm_103a FFMA2) ----------
__device__ __forceinline__ u64 pk2(float x, float y) {
    u64 r;
    asm("mov.b64 %0, {%1, %2};" : "=l"(r) : "r"(__float_as_uint(x)), "r"(__float_as_uint(y)));
    return r;
}
__device__ __forceinline__ float2 up2(u64 v) {
    unsigned lo, hi;
    asm("mov.b64 {%0, %1}, %2;" : "=r"(lo), "=r"(hi) : "l"(v));
    return make_float2(__uint_as_float(lo), __uint_as_float(hi));
}
__device__ __forceinline__ u64 ffma2(u64 a, u64 b, u64 c) {
    u64 d;
    asm("fma.rn.f32x2 %0, %1, %2, %3;" : "=l"(d) : "l"(a), "l"(b), "l"(c));
    return d;
}

// ---------- device scratch ----------
__device__ int   g_deg[NN];
__device__ int   g_rowptr[NN + 1];
__device__ int   g_cursor[NN];
__device__ float g_dis[NN];
__device__ int   g_bsum[64];
__device__ int   g_boff[64];
__device__ int   g_rowS[EE];
__device__ float g_wS[EE];
__device__ float g_eaS[(size_t)EE * DE];
__device__ float g_S[(size_t)NN * DH * LLAY];
__device__ float g_hx[(size_t)NN * DH];
__device__ float g_Q[(size_t)NN * DH * LLAY];
__device__ float g_h[(size_t)NN * DH];

// ---------- CSR build ----------
__global__ void k_zero() {
    int i = blockIdx.x * blockDim.x + threadIdx.x;
    if (i < NN) g_deg[i] = 0;
}

__global__ void k_hist(const int* __restrict__ col) {
    int e = blockIdx.x * blockDim.x + threadIdx.x;
    if (e < EE) atomicAdd(&g_deg[col[e]], 1);
}

// phase 1: per-block scan of deg (local exclusive into rowptr), block totals, plus dis
__global__ void k_part() {
    __shared__ int sh[32];
    int b = blockIdx.x, tid = threadIdx.x;
    int i = b * 1024 + tid;
    int v = (i < NN) ? g_deg[i] : 0;
    if (i < NN) g_dis[i] = (v > 0) ? rsqrtf((float)v) : 0.0f;
    int lane = tid & 31, wid = tid >> 5;
    int x = v;
    #pragma unroll
    for (int off = 1; off < 32; off <<= 1) {
        int t = __shfl_up_sync(0xffffffffu, x, off);
        if (lane >= off) x += t;
    }
    if (lane == 31) sh[wid] = x;
    __syncthreads();
    if (wid == 0) {
        int y = sh[lane];
        #pragma unroll
        for (int off = 1; off < 32; off <<= 1) {
            int t = __shfl_up_sync(0xffffffffu, y, off);
            if (lane >= off) y += t;
        }
        sh[lane] = y;
    }
    __syncthreads();
    int excl = x - v + ((wid > 0) ? sh[wid - 1] : 0);
    if (i < NN) g_rowptr[i] = excl;
    if (tid == 1023) g_bsum[b] = sh[31];
}

// phase 2: scan 49 block sums (one small block, Hillis-Steele in smem)
__global__ void k_off() {
    __shared__ int s[64];
    int t = threadIdx.x;
    int v = (t < NBLK) ? g_bsum[t] : 0;
    s[t] = v;
    __syncthreads();
    #pragma unroll
    for (int off = 1; off < 64; off <<= 1) {
        int tv = (t >= off) ? s[t - off] : 0;
        __syncthreads();
        s[t] += tv;
        __syncthreads();
    }
    g_boff[t] = s[t] - v;  // exclusive
}

// phase 3: add block offsets
__global__ void k_add() {
    int b = blockIdx.x, tid = threadIdx.x;
    int i = b * 1024 + tid;
    if (i < NN) {
        int r = g_rowptr[i] + g_boff[b];
        g_rowptr[i] = r;
        g_cursor[i] = r;
    }
    if (b == 0 && tid == 0) g_rowptr[NN] = EE;
}

__global__ void k_scatter(const int* __restrict__ row, const int* __restrict__ col,
                          const float* __restrict__ ea) {
    int e = blockIdx.x * blockDim.x + threadIdx.x;
    if (e >= EE) return;
    int c = col[e];
    int r = row[e];
    int pos = atomicAdd(&g_cursor[c], 1);
    g_rowS[pos] = r;
    g_wS[pos]   = g_dis[r] * g_dis[c];
    const float4* s = (const float4*)(ea + (size_t)e * DE);
    float4* d = (float4*)(g_eaS + (size_t)pos * DE);
    d[0] = s[0]; d[1] = s[1]; d[2] = s[2]; d[3] = s[3];
}

// ---------- edge-MLP hidden + segment sum, k-pair packed, no shuffles ----------
__device__ __forceinline__ void edge_accum(const u64* __restrict__ wp, const u64 binit[4],
                                           ulonglong2 ea, ulonglong2 eb,
                                           ulonglong2 ec, ulonglong2 ed,
                                           float acc[4]) {
    #pragma unroll
    for (int j = 0; j < 4; j++) {
        const u64* w = wp + j * 8;
        u64 t = ffma2(ea.x, w[0], binit[j]);
        t = ffma2(ea.y, w[1], t);
        t = ffma2(eb.x, w[2], t);
        t = ffma2(eb.y, w[3], t);
        t = ffma2(ec.x, w[4], t);
        t = ffma2(ec.y, w[5], t);
        t = ffma2(ed.x, w[6], t);
        t = ffma2(ed.y, w[7], t);
        float2 f = up2(t);
        acc[j] += fmaxf(f.x + f.y, 0.0f);
    }
}

__global__ __launch_bounds__(256) void k_spass(const float* __restrict__ ew1,
                                               const float* __restrict__ eb1) {
    int gw   = (blockIdx.x * blockDim.x + threadIdx.x) >> 5;
    int lane = threadIdx.x & 31;
    if (gw >= NN * LLAY) return;
    int v = gw / LLAY;
    int l = gw - v * LLAY;
    int d0 = lane * 4;

    // W1 slice as k-pair packed f32x2: wp[j*8+kp] = (W1[2kp][d0+j], W1[2kp+1][d0+j])
    u64 wp[32];
    const float* W1 = ew1 + (size_t)l * DE * DH;
    #pragma unroll
    for (int kp = 0; kp < 8; kp++) {
        float4 r0 = *(const float4*)(W1 + (2 * kp)     * DH + d0);
        float4 r1 = *(const float4*)(W1 + (2 * kp + 1) * DH + d0);
        wp[0 * 8 + kp] = pk2(r0.x, r1.x);
        wp[1 * 8 + kp] = pk2(r0.y, r1.y);
        wp[2 * 8 + kp] = pk2(r0.z, r1.z);
        wp[3 * 8 + kp] = pk2(r0.w, r1.w);
    }
    float4 b1 = *(const float4*)(eb1 + l * DH + d0);
    u64 binit[4] = { pk2(b1.x, 0.f), pk2(b1.y, 0.f), pk2(b1.z, 0.f), pk2(b1.w, 0.f) };

    float acc[4] = {0.f, 0.f, 0.f, 0.f};
    int e0 = g_rowptr[v], e1 = g_rowptr[v + 1];
    int e = e0;
    for (; e + 1 < e1; e += 2) {
        const ulonglong2* p0 = (const ulonglong2*)(g_eaS + (size_t)e * DE);
        const ulonglong2* p1 = (const ulonglong2*)(g_eaS + (size_t)(e + 1) * DE);
        ulonglong2 a0 = p0[0], b0 = p0[1], c0 = p0[2], d0v = p0[3];
        ulonglong2 a1 = p1[0], b1v = p1[1], c1 = p1[2], d1 = p1[3];
        edge_accum(wp, binit, a0, b0, c0, d0v, acc);
        edge_accum(wp, binit, a1, b1v, c1, d1, acc);
    }
    if (e < e1) {
        const ulonglong2* p0 = (const ulonglong2*)(g_eaS + (size_t)e * DE);
        edge_accum(wp, binit, p0[0], p0[1], p0[2], p0[3], acc);
    }
    *(float4*)(g_S + (size_t)v * (DH * LLAY) + l * DH + d0) =
        make_float4(acc[0], acc[1], acc[2], acc[3]);
}

// ---------- dense GEMM body: C[M,128] = A[M,*] @ B[128,128] ----------
__device__ __forceinline__ void gemm_body(const float* __restrict__ A, int lda,
                                          const float* __restrict__ B,
                                          float* __restrict__ C, int M,
                                          float* sm, int bx) {
    float* As = sm;                      // 64 x 128 f32
    u64* Bsp  = (u64*)(sm + 64 * 128);   // [64 kk][128 c] k-paired
    int tid = threadIdx.x;               // 256
    int m0  = bx * 64;

    #pragma unroll
    for (int i = 0; i < 8; i++) {
        int lin = (i * 256 + tid) * 4;
        int r = lin >> 7, k = lin & 127;
        float4 vv = make_float4(0.f, 0.f, 0.f, 0.f);
        if (m0 + r < M) vv = *(const float4*)(A + (size_t)(m0 + r) * lda + k);
        *(float4*)(As + lin) = vv;
    }
    #pragma unroll
    for (int i = 0; i < 32; i++) {
        int idx = i * 256 + tid;
        int kk = idx >> 7, c = idx & 127;
        Bsp[idx] = pk2(B[(2 * kk) * 128 + c], B[(2 * kk + 1) * 128 + c]);
    }
    __syncthreads();

    int cbase = (tid & 31) * 4;
    int rbase = (tid >> 5) * 8;
    u64 acc[8][4];
    #pragma unroll
    for (int i = 0; i < 8; i++) {
        acc[i][0] = 0ull; acc[i][1] = 0ull; acc[i][2] = 0ull; acc[i][3] = 0ull;
    }
    const u64* Asd = (const u64*)As;
    #pragma unroll 8
    for (int kk = 0; kk < 64; kk++) {
        const ulonglong2* bp = (const ulonglong2*)(Bsp + kk * 128 + cbase);
        ulonglong2 b01 = bp[0];
        ulonglong2 b23 = bp[1];
        #pragma unroll
        for (int i = 0; i < 8; i++) {
            u64 a = Asd[(size_t)(rbase + i) * 64 + kk];
            acc[i][0] = ffma2(a, b01.x, acc[i][0]);
            acc[i][1] = ffma2(a, b01.y, acc[i][1]);
            acc[i][2] = ffma2(a, b23.x, acc[i][2]);
            acc[i][3] = ffma2(a, b23.y, acc[i][3]);
        }
    }
    #pragma unroll
    for (int i = 0; i < 8; i++) {
        int r = m0 + rbase + i;
        if (r < M) {
            float2 t0 = up2(acc[i][0]), t1 = up2(acc[i][1]);
            float2 t2 = up2(acc[i][2]), t3 = up2(acc[i][3]);
            float4 o = make_float4(t0.x + t0.y, t1.x + t1.y, t2.x + t2.y, t3.x + t3.y);
            *(float4*)(C + (size_t)r * 128 + cbase) = o;
        }
    }
}

// batched: y==0 -> hx0 = x@linW0 ; y==1..3 -> Q_l = S_l@W2_l
__global__ __launch_bounds__(256) void k_gemm4(const float* __restrict__ x,
                                               const float* __restrict__ linw,
                                               const float* __restrict__ ew2) {
    extern __shared__ float sm[];
    const float* A; int lda; const float* B; float* C;
    if (blockIdx.y == 0) {
        A = x; lda = 128; B = linw; C = g_hx;
    } else {
        int l = blockIdx.y - 1;
        A = g_S + l * DH; lda = DH * LLAY;
        B = ew2 + (size_t)l * DH * DH;
        C = g_Q + (size_t)l * NN * DH;
    }
    gemm_body(A, lda, B, C, NN, sm, blockIdx.x);
}

__global__ __launch_bounds__(256) void k_gemm(const float* __restrict__ A, int lda,
                                              const float* __restrict__ B,
                                              float* __restrict__ C, int M) {
    extern __shared__ float sm[];
    gemm_body(A, lda, B, C, M, sm, blockIdx.x);
}

// ---------- gather + aggregate + LayerNorm + ReLU (one warp per node) ----------
__global__ void k_msgln(const float* __restrict__ hx, const float* __restrict__ Q,
                        const float* __restrict__ b2, const float* __restrict__ bi,
                        const float* __restrict__ lw, const float* __restrict__ lb,
                        float* __restrict__ out) {
    int gt = blockIdx.x * blockDim.x + threadIdx.x;
    int v = gt >> 5, lane = gt & 31;
    if (v >= NN) return;
    int d0 = lane * 4;
    float a0 = 0.f, a1 = 0.f, a2 = 0.f, a3 = 0.f;
    int e0 = g_rowptr[v], e1 = g_rowptr[v + 1];
    for (int base = e0; base < e1; base += 32) {
        int idx = base + lane;
        int   rr = (idx < e1) ? g_rowS[idx] : 0;
        float ww = (idx < e1) ? g_wS[idx] : 0.f;
        int n = min(32, e1 - base);
        #pragma unroll 4
        for (int j = 0; j < n; j++) {
            int   r = __shfl_sync(0xffffffffu, rr, j);
            float w = __shfl_sync(0xffffffffu, ww, j);
            float4 hv = *(const float4*)(hx + (size_t)r * 128 + d0);
            a0 = fmaf(w, hv.x, a0);
            a1 = fmaf(w, hv.y, a1);
            a2 = fmaf(w, hv.z, a2);
            a3 = fmaf(w, hv.w, a3);
        }
    }
    float degf = (float)g_deg[v];
    float4 q  = *(const float4*)(Q + (size_t)v * 128 + d0);
    float4 c2 = *(const float4*)(b2 + d0);
    float4 cb = *(const float4*)(bi + d0);
    float x0 = a0 + q.x + degf * c2.x + cb.x;
    float x1 = a1 + q.y + degf * c2.y + cb.y;
    float x2 = a2 + q.z + degf * c2.z + cb.z;
    float x3 = a3 + q.w + degf * c2.w + cb.w;
    float s = x0 + x1 + x2 + x3;
    #pragma unroll
    for (int off = 16; off; off >>= 1) s += __shfl_xor_sync(0xffffffffu, s, off);
    float mu = s * (1.0f / 128.0f);
    float e0f = x0 - mu, e1f = x1 - mu, e2f = x2 - mu, e3f = x3 - mu;
    float vs = e0f * e0f + e1f * e1f + e2f * e2f + e3f * e3f;
    #pragma unroll
    for (int off = 16; off; off >>= 1) vs += __shfl_xor_sync(0xffffffffu, vs, off);
    float inv = rsqrtf(vs * (1.0f / 128.0f) + 1e-5f);
    float4 w4 = *(const float4*)(lw + d0);
    float4 b4 = *(const float4*)(lb + d0);
    float4 o;
    o.x = fmaxf(e0f * inv * w4.x + b4.x, 0.f);
    o.y = fmaxf(e1f * inv * w4.y + b4.y, 0.f);
    o.z = fmaxf(e2f * inv * w4.z + b4.z, 0.f);
    o.w = fmaxf(e3f * inv * w4.w + b4.w, 0.f);
    *(float4*)(out + (size_t)v * 128 + d0) = o;
}

extern "C" void kernel_launch(void* const* d_in, const int* in_sizes, int n_in,
                              void* d_out, int out_size) {
    const float* x    = (const float*)d_in[0];
    const float* ea   = (const float*)d_in[1];
    const float* linw = (const float*)d_in[2];
    const float* ew1  = (const float*)d_in[3];
    const float* eb1  = (const float*)d_in[4];
    const float* ew2  = (const float*)d_in[5];
    const float* eb2  = (const float*)d_in[6];
    const float* bias = (const float*)d_in[7];
    const float* lnw  = (const float*)d_in[8];
    const float* lnb  = (const float*)d_in[9];
    const int*   eidx = (const int*)d_in[10];
    const int* rowp = eidx;
    const int* colp = eidx + EE;
    float* out = (float*)d_out;

    cudaFuncSetAttribute(k_gemm,  cudaFuncAttributeMaxDynamicSharedMemorySize, 98304);
    cudaFuncSetAttribute(k_gemm4, cudaFuncAttributeMaxDynamicSharedMemorySize, 98304);

    float *hx, *Q, *h;
    cudaGetSymbolAddress((void**)&hx, g_hx);
    cudaGetSymbolAddress((void**)&Q,  g_Q);
    cudaGetSymbolAddress((void**)&h,  g_h);

    // CSR build (parallel 3-phase scan)
    k_zero<<<(NN + 255) / 256, 256>>>();
    k_hist<<<(EE + 255) / 256, 256>>>(colp);
    k_part<<<NBLK, 1024>>>();
    k_off<<<1, 64>>>();
    k_add<<<NBLK, 1024>>>();
    k_scatter<<<(EE + 255) / 256, 256>>>(rowp, colp, ea);

    // edge-MLP hidden + segment-sum, all 3 layers
    k_spass<<<(NN * LLAY * 32 + 255) / 256, 256>>>(ew1, eb1);

    // batched: hx0 + Q0..Q2 in one launch
    {
        dim3 grid((NN + 63) / 64, 4);
        k_gemm4<<<grid, 256, 98304>>>(x, linw, ew2);
    }

    for (int l = 0; l < LLAY; l++) {
        if (l > 0)
            k_gemm<<<(NN + 63) / 64, 256, 98304>>>(h, 128, linw + (size_t)l * 128 * 128, hx, NN);
        float* ho = (l == LLAY - 1) ? out : h;
        k_msgln<<<(NN * 32 + 255) / 256, 256>>>(hx, Q + (size_t)l * NN * DH,
                                                eb2 + l * 128, bias + l * 128,
                                                lnw + l * 128, lnb + l * 128, ho);
    }
}

// round 4
// speedup vs baseline: 1.2366x; 1.2366x over previous
#include <cuda_runtime.h>

#define NN 50000
#define EE 800000
#define DH 128
#define DE 16
#define LLAY 3
#define NBLK 49   // ceil(NN/1024)

typedef unsigned long long u64;

// ---------- packed f32x2 helpers (sm_103a FFMA2) ----------
__device__ __forceinline__ u64 pk2(float x, float y) {
    u64 r;
    asm("mov.b64 %0, {%1, %2};" : "=l"(r) : "r"(__float_as_uint(x)), "r"(__float_as_uint(y)));
    return r;
}
__device__ __forceinline__ float2 up2(u64 v) {
    unsigned lo, hi;
    asm("mov.b64 {%0, %1}, %2;" : "=r"(lo), "=r"(hi) : "l"(v));
    return make_float2(__uint_as_float(lo), __uint_as_float(hi));
}
__device__ __forceinline__ u64 ffma2(u64 a, u64 b, u64 c) {
    u64 d;
    asm("fma.rn.f32x2 %0, %1, %2, %3;" : "=l"(d) : "l"(a), "l"(b), "l"(c));
    return d;
}

// ---------- device scratch ----------
__device__ int   g_deg[NN];
__device__ int   g_rowptr[NN + 1];
__device__ int   g_cursor[NN];
__device__ float g_dis[NN];
__device__ int   g_bsum[64];
__device__ int   g_boff[64];
__device__ int   g_rowS[EE];
__device__ float g_wS[EE];
__device__ float g_eaS[(size_t)EE * DE];
__device__ float g_S[(size_t)NN * DH * LLAY];
__device__ float g_hx[(size_t)NN * DH];
__device__ float g_Q[(size_t)NN * DH * LLAY];
__device__ float g_h[(size_t)NN * DH];

// ---------- CSR build ----------
__global__ void k_zero() {
    int i = blockIdx.x * blockDim.x + threadIdx.x;
    if (i < NN) g_deg[i] = 0;
}

__global__ void k_hist(const int* __restrict__ col) {
    int e = blockIdx.x * blockDim.x + threadIdx.x;
    if (e < EE) atomicAdd(&g_deg[col[e]], 1);
}

// phase 1: per-block scan of deg (local exclusive into rowptr), block totals, plus dis
__global__ void k_part() {
    __shared__ int sh[32];
    int b = blockIdx.x, tid = threadIdx.x;
    int i = b * 1024 + tid;
    int v = (i < NN) ? g_deg[i] : 0;
    if (i < NN) g_dis[i] = (v > 0) ? rsqrtf((float)v) : 0.0f;
    int lane = tid & 31, wid = tid >> 5;
    int x = v;
    #pragma unroll
    for (int off = 1; off < 32; off <<= 1) {
        int t = __shfl_up_sync(0xffffffffu, x, off);
        if (lane >= off) x += t;
    }
    if (lane == 31) sh[wid] = x;
    __syncthreads();
    if (wid == 0) {
        int y = sh[lane];
        #pragma unroll
        for (int off = 1; off < 32; off <<= 1) {
            int t = __shfl_up_sync(0xffffffffu, y, off);
            if (lane >= off) y += t;
        }
        sh[lane] = y;
    }
    __syncthreads();
    int excl = x - v + ((wid > 0) ? sh[wid - 1] : 0);
    if (i < NN) g_rowptr[i] = excl;
    if (tid == 1023) g_bsum[b] = sh[31];
}

// phase 2: scan 49 block sums (one small block, Hillis-Steele in smem)
__global__ void k_off() {
    __shared__ int s[64];
    int t = threadIdx.x;
    int v = (t < NBLK) ? g_bsum[t] : 0;
    s[t] = v;
    __syncthreads();
    #pragma unroll
    for (int off = 1; off < 64; off <<= 1) {
        int tv = (t >= off) ? s[t - off] : 0;
        __syncthreads();
        s[t] += tv;
        __syncthreads();
    }
    g_boff[t] = s[t] - v;  // exclusive
}

// phase 3: add block offsets
__global__ void k_add() {
    int b = blockIdx.x, tid = threadIdx.x;
    int i = b * 1024 + tid;
    if (i < NN) {
        int r = g_rowptr[i] + g_boff[b];
        g_rowptr[i] = r;
        g_cursor[i] = r;
    }
    if (b == 0 && tid == 0) g_rowptr[NN] = EE;
}

__global__ void k_scatter(const int* __restrict__ row, const int* __restrict__ col,
                          const float* __restrict__ ea) {
    int e = blockIdx.x * blockDim.x + threadIdx.x;
    if (e >= EE) return;
    int c = col[e];
    int r = row[e];
    int pos = atomicAdd(&g_cursor[c], 1);
    g_rowS[pos] = r;
    g_wS[pos]   = g_dis[r] * g_dis[c];
    const float4* s = (const float4*)(ea + (size_t)e * DE);
    float4* d = (float4*)(g_eaS + (size_t)pos * DE);
    d[0] = s[0]; d[1] = s[1]; d[2] = s[2]; d[3] = s[3];
}

// ---------- edge-MLP hidden + segment sum (Round-2 proven version) ----------
// one warp per (node, layer); W1 column slice in registers, ea broadcast via shfl
__global__ __launch_bounds__(256) void k_spass(const float* __restrict__ ew1,
                                               const float* __restrict__ eb1) {
    int gw   = (blockIdx.x * blockDim.x + threadIdx.x) >> 5;
    int lane = threadIdx.x & 31;
    if (gw >= NN * LLAY) return;
    int v = gw / LLAY;
    int l = gw - v * LLAY;
    int d0 = lane * 4;

    u64 w1lo[16], w1hi[16];
    const float* W1 = ew1 + (size_t)l * DE * DH;
    #pragma unroll
    for (int k = 0; k < 16; k++) {
        float4 t = *(const float4*)(W1 + k * DH + d0);
        w1lo[k] = pk2(t.x, t.y);
        w1hi[k] = pk2(t.z, t.w);
    }
    float4 b1 = *(const float4*)(eb1 + l * DH + d0);
    u64 b1lo = pk2(b1.x, b1.y), b1hi = pk2(b1.z, b1.w);

    float a0 = 0.f, a1 = 0.f, a2 = 0.f, a3 = 0.f;
    int e0 = g_rowptr[v], e1 = g_rowptr[v + 1];
    for (int e = e0; e < e1; e++) {
        float eav = (lane < 16) ? g_eaS[(size_t)e * DE + lane] : 0.0f;
        u64 plo = b1lo, phi = b1hi;
        #pragma unroll
        for (int k = 0; k < 16; k++) {
            float ak = __shfl_sync(0xffffffffu, eav, k);
            u64 ak2 = pk2(ak, ak);
            plo = ffma2(ak2, w1lo[k], plo);
            phi = ffma2(ak2, w1hi[k], phi);
        }
        float2 x0 = up2(plo), x1 = up2(phi);
        a0 += fmaxf(x0.x, 0.f);
        a1 += fmaxf(x0.y, 0.f);
        a2 += fmaxf(x1.x, 0.f);
        a3 += fmaxf(x1.y, 0.f);
    }
    *(float4*)(g_S + (size_t)v * (DH * LLAY) + l * DH + d0) =
        make_float4(a0, a1, a2, a3);
}

// ---------- dense GEMM body: C[M,128] = A[M,*] @ B[128,128] ----------
__device__ __forceinline__ void gemm_body(const float* __restrict__ A, int lda,
                                          const float* __restrict__ B,
                                          float* __restrict__ C, int M,
                                          float* sm, int bx) {
    float* As = sm;                      // 64 x 128 f32
    u64* Bsp  = (u64*)(sm + 64 * 128);   // [64 kk][128 c] k-paired
    int tid = threadIdx.x;               // 256
    int m0  = bx * 64;

    #pragma unroll
    for (int i = 0; i < 8; i++) {
        int lin = (i * 256 + tid) * 4;
        int r = lin >> 7, k = lin & 127;
        float4 vv = make_float4(0.f, 0.f, 0.f, 0.f);
        if (m0 + r < M) vv = *(const float4*)(A + (size_t)(m0 + r) * lda + k);
        *(float4*)(As + lin) = vv;
    }
    #pragma unroll
    for (int i = 0; i < 32; i++) {
        int idx = i * 256 + tid;
        int kk = idx >> 7, c = idx & 127;
        Bsp[idx] = pk2(B[(2 * kk) * 128 + c], B[(2 * kk + 1) * 128 + c]);
    }
    __syncthreads();

    int cbase = (tid & 31) * 4;
    int rbase = (tid >> 5) * 8;
    u64 acc[8][4];
    #pragma unroll
    for (int i = 0; i < 8; i++) {
        acc[i][0] = 0ull; acc[i][1] = 0ull; acc[i][2] = 0ull; acc[i][3] = 0ull;
    }
    const u64* Asd = (const u64*)As;
    #pragma unroll 8
    for (int kk = 0; kk < 64; kk++) {
        const ulonglong2* bp = (const ulonglong2*)(Bsp + kk * 128 + cbase);
        ulonglong2 b01 = bp[0];
        ulonglong2 b23 = bp[1];
        #pragma unroll
        for (int i = 0; i < 8; i++) {
            u64 a = Asd[(size_t)(rbase + i) * 64 + kk];
            acc[i][0] = ffma2(a, b01.x, acc[i][0]);
            acc[i][1] = ffma2(a, b01.y, acc[i][1]);
            acc[i][2] = ffma2(a, b23.x, acc[i][2]);
            acc[i][3] = ffma2(a, b23.y, acc[i][3]);
        }
    }
    #pragma unroll
    for (int i = 0; i < 8; i++) {
        int r = m0 + rbase + i;
        if (r < M) {
            float2 t0 = up2(acc[i][0]), t1 = up2(acc[i][1]);
            float2 t2 = up2(acc[i][2]), t3 = up2(acc[i][3]);
            float4 o = make_float4(t0.x + t0.y, t1.x + t1.y, t2.x + t2.y, t3.x + t3.y);
            *(float4*)(C + (size_t)r * 128 + cbase) = o;
        }
    }
}

// batched: y==0 -> hx0 = x@linW0 ; y==1..3 -> Q_l = S_l@W2_l
__global__ __launch_bounds__(256) void k_gemm4(const float* __restrict__ x,
                                               const float* __restrict__ linw,
                                               const float* __restrict__ ew2) {
    extern __shared__ float sm[];
    const float* A; int lda; const float* B; float* C;
    if (blockIdx.y == 0) {
        A = x; lda = 128; B = linw; C = g_hx;
    } else {
        int l = blockIdx.y - 1;
        A = g_S + l * DH; lda = DH * LLAY;
        B = ew2 + (size_t)l * DH * DH;
        C = g_Q + (size_t)l * NN * DH;
    }
    gemm_body(A, lda, B, C, NN, sm, blockIdx.x);
}

__global__ __launch_bounds__(256) void k_gemm(const float* __restrict__ A, int lda,
                                              const float* __restrict__ B,
                                              float* __restrict__ C, int M) {
    extern __shared__ float sm[];
    gemm_body(A, lda, B, C, M, sm, blockIdx.x);
}

// ---------- gather + aggregate + LayerNorm + ReLU (one warp per node) ----------
__global__ void k_msgln(const float* __restrict__ hx, const float* __restrict__ Q,
                        const float* __restrict__ b2, const float* __restrict__ bi,
                        const float* __restrict__ lw, const float* __restrict__ lb,
                        float* __restrict__ out) {
    int gt = blockIdx.x * blockDim.x + threadIdx.x;
    int v = gt >> 5, lane = gt & 31;
    if (v >= NN) return;
    int d0 = lane * 4;
    float a0 = 0.f, a1 = 0.f, a2 = 0.f, a3 = 0.f;
    int e0 = g_rowptr[v], e1 = g_rowptr[v + 1];
    for (int base = e0; base < e1; base += 32) {
        int idx = base + lane;
        int   rr = (idx < e1) ? g_rowS[idx] : 0;
        float ww = (idx < e1) ? g_wS[idx] : 0.f;
        int n = min(32, e1 - base);
        #pragma unroll 4
        for (int j = 0; j < n; j++) {
            int   r = __shfl_sync(0xffffffffu, rr, j);
            float w = __shfl_sync(0xffffffffu, ww, j);
            float4 hv = *(const float4*)(hx + (size_t)r * 128 + d0);
            a0 = fmaf(w, hv.x, a0);
            a1 = fmaf(w, hv.y, a1);
            a2 = fmaf(w, hv.z, a2);
            a3 = fmaf(w, hv.w, a3);
        }
    }
    float degf = (float)g_deg[v];
    float4 q  = *(const float4*)(Q + (size_t)v * 128 + d0);
    float4 c2 = *(const float4*)(b2 + d0);
    float4 cb = *(const float4*)(bi + d0);
    float x0 = a0 + q.x + degf * c2.x + cb.x;
    float x1 = a1 + q.y + degf * c2.y + cb.y;
    float x2 = a2 + q.z + degf * c2.z + cb.z;
    float x3 = a3 + q.w + degf * c2.w + cb.w;
    float s = x0 + x1 + x2 + x3;
    #pragma unroll
    for (int off = 16; off; off >>= 1) s += __shfl_xor_sync(0xffffffffu, s, off);
    float mu = s * (1.0f / 128.0f);
    float e0f = x0 - mu, e1f = x1 - mu, e2f = x2 - mu, e3f = x3 - mu;
    float vs = e0f * e0f + e1f * e1f + e2f * e2f + e3f * e3f;
    #pragma unroll
    for (int off = 16; off; off >>= 1) vs += __shfl_xor_sync(0xffffffffu, vs, off);
    float inv = rsqrtf(vs * (1.0f / 128.0f) + 1e-5f);
    float4 w4 = *(const float4*)(lw + d0);
    float4 b4 = *(const float4*)(lb + d0);
    float4 o;
    o.x = fmaxf(e0f * inv * w4.x + b4.x, 0.f);
    o.y = fmaxf(e1f * inv * w4.y + b4.y, 0.f);
    o.z = fmaxf(e2f * inv * w4.z + b4.z, 0.f);
    o.w = fmaxf(e3f * inv * w4.w + b4.w, 0.f);
    *(float4*)(out + (size_t)v * 128 + d0) = o;
}

extern "C" void kernel_launch(void* const* d_in, const int* in_sizes, int n_in,
                              void* d_out, int out_size) {
    const float* x    = (const float*)d_in[0];
    const float* ea   = (const float*)d_in[1];
    const float* linw = (const float*)d_in[2];
    const float* ew1  = (const float*)d_in[3];
    const float* eb1  = (const float*)d_in[4];
    const float* ew2  = (const float*)d_in[5];
    const float* eb2  = (const float*)d_in[6];
    const float* bias = (const float*)d_in[7];
    const float* lnw  = (const float*)d_in[8];
    const float* lnb  = (const float*)d_in[9];
    const int*   eidx = (const int*)d_in[10];
    const int* rowp = eidx;
    const int* colp = eidx + EE;
    float* out = (float*)d_out;

    cudaFuncSetAttribute(k_gemm,  cudaFuncAttributeMaxDynamicSharedMemorySize, 98304);
    cudaFuncSetAttribute(k_gemm4, cudaFuncAttributeMaxDynamicSharedMemorySize, 98304);

    float *hx, *Q, *h;
    cudaGetSymbolAddress((void**)&hx, g_hx);
    cudaGetSymbolAddress((void**)&Q,  g_Q);
    cudaGetSymbolAddress((void**)&h,  g_h);

    // CSR build (parallel 3-phase scan)
    k_zero<<<(NN + 255) / 256, 256>>>();
    k_hist<<<(EE + 255) / 256, 256>>>(colp);
    k_part<<<NBLK, 1024>>>();
    k_off<<<1, 64>>>();
    k_add<<<NBLK, 1024>>>();
    k_scatter<<<(EE + 255) / 256, 256>>>(rowp, colp, ea);

    // edge-MLP hidden + segment-sum, all 3 layers
    k_spass<<<(NN * LLAY * 32 + 255) / 256, 256>>>(ew1, eb1);

    // batched: hx0 + Q0..Q2 in one launch
    {
        dim3 grid((NN + 63) / 64, 4);
        k_gemm4<<<grid, 256, 98304>>>(x, linw, ew2);
    }

    for (int l = 0; l < LLAY; l++) {
        if (l > 0)
            k_gemm<<<(NN + 63) / 64, 256, 98304>>>(h, 128, linw + (size_t)l * 128 * 128, hx, NN);
        float* ho = (l == LLAY - 1) ? out : h;
        k_msgln<<<(NN * 32 + 255) / 256, 256>>>(hx, Q + (size_t)l * NN * DH,
                                                eb2 + l * 128, bias + l * 128,
                                                lnw + l * 128, lnb + l * 128, ho);
    }
}

// round 6
// speedup vs baseline: 1.5871x; 1.2834x over previous
#include <cuda_runtime.h>

#define NN 50000
#define EE 800000
#define DH 128
#define DE 16
#define LLAY 3
#define NBLK 49   // ceil(NN/1024)

typedef unsigned long long u64;

// ---------- packed f32x2 helpers (sm_103a FFMA2) ----------
__device__ __forceinline__ u64 pk2(float x, float y) {
    u64 r;
    asm("mov.b64 %0, {%1, %2};" : "=l"(r) : "r"(__float_as_uint(x)), "r"(__float_as_uint(y)));
    return r;
}
__device__ __forceinline__ float2 up2(u64 v) {
    unsigned lo, hi;
    asm("mov.b64 {%0, %1}, %2;" : "=r"(lo), "=r"(hi) : "l"(v));
    return make_float2(__uint_as_float(lo), __uint_as_float(hi));
}
__device__ __forceinline__ u64 ffma2(u64 a, u64 b, u64 c) {
    u64 d;
    asm("fma.rn.f32x2 %0, %1, %2, %3;" : "=l"(d) : "l"(a), "l"(b), "l"(c));
    return d;
}

// ---------- device scratch ----------
__device__ int   g_deg[NN];
__device__ int   g_rowptr[NN + 1];
__device__ int   g_cursor[NN];
__device__ float g_dis[NN];
__device__ int   g_bsum[64];
__device__ int   g_boff[64];
__device__ int   g_rowS[EE];
__device__ float g_wS[EE];
__device__ float g_eaS[(size_t)EE * DE];
__device__ float g_S[(size_t)NN * DH * LLAY];
__device__ float g_hx[(size_t)NN * DH];
__device__ float g_Q[(size_t)NN * DH * LLAY];
__device__ float g_h[(size_t)NN * DH];

// ---------- CSR build ----------
__global__ void k_zero() {
    int i = blockIdx.x * blockDim.x + threadIdx.x;
    if (i < NN) g_deg[i] = 0;
}

__global__ void k_hist(const int* __restrict__ col) {
    int e = blockIdx.x * blockDim.x + threadIdx.x;
    if (e < EE) atomicAdd(&g_deg[col[e]], 1);
}

// phase 1: per-block scan of deg (local exclusive into rowptr), block totals, plus dis
__global__ void k_part() {
    __shared__ int sh[32];
    int b = blockIdx.x, tid = threadIdx.x;
    int i = b * 1024 + tid;
    int v = (i < NN) ? g_deg[i] : 0;
    if (i < NN) g_dis[i] = (v > 0) ? rsqrtf((float)v) : 0.0f;
    int lane = tid & 31, wid = tid >> 5;
    int x = v;
    #pragma unroll
    for (int off = 1; off < 32; off <<= 1) {
        int t = __shfl_up_sync(0xffffffffu, x, off);
        if (lane >= off) x += t;
    }
    if (lane == 31) sh[wid] = x;
    __syncthreads();
    if (wid == 0) {
        int y = sh[lane];
        #pragma unroll
        for (int off = 1; off < 32; off <<= 1) {
            int t = __shfl_up_sync(0xffffffffu, y, off);
            if (lane >= off) y += t;
        }
        sh[lane] = y;
    }
    __syncthreads();
    int excl = x - v + ((wid > 0) ? sh[wid - 1] : 0);
    if (i < NN) g_rowptr[i] = excl;
    if (tid == 1023) g_bsum[b] = sh[31];
}

// phase 2: scan 49 block sums
__global__ void k_off() {
    __shared__ int s[64];
    int t = threadIdx.x;
    int v = (t < NBLK) ? g_bsum[t] : 0;
    s[t] = v;
    __syncthreads();
    #pragma unroll
    for (int off = 1; off < 64; off <<= 1) {
        int tv = (t >= off) ? s[t - off] : 0;
        __syncthreads();
        s[t] += tv;
        __syncthreads();
    }
    g_boff[t] = s[t] - v;  // exclusive
}

// phase 3: add block offsets
__global__ void k_add() {
    int b = blockIdx.x, tid = threadIdx.x;
    int i = b * 1024 + tid;
    if (i < NN) {
        int r = g_rowptr[i] + g_boff[b];
        g_rowptr[i] = r;
        g_cursor[i] = r;
    }
    if (b == 0 && tid == 0) g_rowptr[NN] = EE;
}

__global__ void k_scatter(const int* __restrict__ row, const int* __restrict__ col,
                          const float* __restrict__ ea) {
    int e = blockIdx.x * blockDim.x + threadIdx.x;
    if (e >= EE) return;
    int c = col[e];
    int r = row[e];
    int pos = atomicAdd(&g_cursor[c], 1);
    g_rowS[pos] = r;
    g_wS[pos]   = g_dis[r] * g_dis[c];
    const float4* s = (const float4*)(ea + (size_t)e * DE);
    float4* d = (float4*)(g_eaS + (size_t)pos * DE);
    d[0] = s[0]; d[1] = s[1]; d[2] = s[2]; d[3] = s[3];
}

// ---------- edge-MLP hidden + segment sum: smem-staged broadcast LDS version ----------
// one warp per (node, layer); W1 k-pair packed in regs; edge k-pairs read as
// broadcast LDS.64 from a warp-private staging buffer (no SHFL, no dup MOVs)
__global__ __launch_bounds__(256) void k_spass(const float* __restrict__ ew1,
                                               const float* __restrict__ eb1) {
    __shared__ __align__(16) float sEdge[8][32 * DE];   // 2KB per warp
    int wIn  = threadIdx.x >> 5;
    int gw   = (blockIdx.x * blockDim.x + threadIdx.x) >> 5;
    int lane = threadIdx.x & 31;
    if (gw >= NN * LLAY) return;
    int v = gw / LLAY;
    int l = gw - v * LLAY;
    int d0 = lane * 4;

    // W1 slice k-pair packed: wp[j][kp] = (W1[2kp][d0+j], W1[2kp+1][d0+j])
    u64 wp[4][8];
    const float* W1 = ew1 + (size_t)l * DE * DH;
    #pragma unroll
    for (int kp = 0; kp < 8; kp++) {
        float4 r0 = *(const float4*)(W1 + (2 * kp)     * DH + d0);
        float4 r1 = *(const float4*)(W1 + (2 * kp + 1) * DH + d0);
        wp[0][kp] = pk2(r0.x, r1.x);
        wp[1][kp] = pk2(r0.y, r1.y);
        wp[2][kp] = pk2(r0.z, r1.z);
        wp[3][kp] = pk2(r0.w, r1.w);
    }
    float4 b1 = *(const float4*)(eb1 + l * DH + d0);
    u64 binit[4] = { pk2(b1.x, 0.f), pk2(b1.y, 0.f), pk2(b1.z, 0.f), pk2(b1.w, 0.f) };

    float acc[4] = {0.f, 0.f, 0.f, 0.f};
    int e0 = g_rowptr[v], e1 = g_rowptr[v + 1];
    float* buf = sEdge[wIn];
    for (int base = e0; base < e1; base += 32) {
        int n = min(32, e1 - base);
        __syncwarp();   // WAR: prior iteration's LDS reads done before restage
        const float4* src = (const float4*)(g_eaS + (size_t)base * DE);
        #pragma unroll
        for (int c = 0; c < 4; c++) {
            int idx = c * 32 + lane;
            if (idx < n * 4) ((float4*)buf)[idx] = src[idx];
        }
        __syncwarp();
        for (int i = 0; i < n; i++) {
            const u64* ep = (const u64*)(buf + i * DE);  // 8 k-pairs, uniform addr -> broadcast
            #pragma unroll
            for (int j = 0; j < 4; j++) {
                u64 t = binit[j];
                #pragma unroll
                for (int kp = 0; kp < 8; kp++)
                    t = ffma2(ep[kp], wp[j][kp], t);
                float2 f = up2(t);
                acc[j] += fmaxf(f.x + f.y, 0.0f);
            }
        }
    }
    *(float4*)(g_S + (size_t)v * (DH * LLAY) + l * DH + d0) =
        make_float4(acc[0], acc[1], acc[2], acc[3]);
}

// ---------- dense GEMM body: C[M,128] = A[M,*] @ B[128,128] ----------
__device__ __forceinline__ void gemm_body(const float* __restrict__ A, int lda,
                                          const float* __restrict__ B,
                                          float* __restrict__ C, int M,
                                          float* sm, int bx) {
    float* As = sm;                      // 64 x 128 f32
    u64* Bsp  = (u64*)(sm + 64 * 128);   // [64 kk][128 c] k-paired
    int tid = threadIdx.x;               // 256
    int m0  = bx * 64;

    #pragma unroll
    for (int i = 0; i < 8; i++) {
        int lin = (i * 256 + tid) * 4;
        int r = lin >> 7, k = lin & 127;
        float4 vv = make_float4(0.f, 0.f, 0.f, 0.f);
        if (m0 + r < M) vv = *(const float4*)(A + (size_t)(m0 + r) * lda + k);
        *(float4*)(As + lin) = vv;
    }
    #pragma unroll
    for (int i = 0; i < 32; i++) {
        int idx = i * 256 + tid;
        int kk = idx >> 7, c = idx & 127;
        Bsp[idx] = pk2(B[(2 * kk) * 128 + c], B[(2 * kk + 1) * 128 + c]);
    }
    __syncthreads();

    int cbase = (tid & 31) * 4;
    int rbase = (tid >> 5) * 8;
    u64 acc[8][4];
    #pragma unroll
    for (int i = 0; i < 8; i++) {
        acc[i][0] = 0ull; acc[i][1] = 0ull; acc[i][2] = 0ull; acc[i][3] = 0ull;
    }
    const u64* Asd = (const u64*)As;
    #pragma unroll 8
    for (int kk = 0; kk < 64; kk++) {
        const ulonglong2* bp = (const ulonglong2*)(Bsp + kk * 128 + cbase);
        ulonglong2 b01 = bp[0];
        ulonglong2 b23 = bp[1];
        #pragma unroll
        for (int i = 0; i < 8; i++) {
            u64 a = Asd[(size_t)(rbase + i) * 64 + kk];
            acc[i][0] = ffma2(a, b01.x, acc[i][0]);
            acc[i][1] = ffma2(a, b01.y, acc[i][1]);
            acc[i][2] = ffma2(a, b23.x, acc[i][2]);
            acc[i][3] = ffma2(a, b23.y, acc[i][3]);
        }
    }
    #pragma unroll
    for (int i = 0; i < 8; i++) {
        int r = m0 + rbase + i;
        if (r < M) {
            float2 t0 = up2(acc[i][0]), t1 = up2(acc[i][1]);
            float2 t2 = up2(acc[i][2]), t3 = up2(acc[i][3]);
            float4 o = make_float4(t0.x + t0.y, t1.x + t1.y, t2.x + t2.y, t3.x + t3.y);
            *(float4*)(C + (size_t)r * 128 + cbase) = o;
        }
    }
}

// batched: y==0 -> hx0 = x@linW0 ; y==1..3 -> Q_l = S_l@W2_l
__global__ __launch_bounds__(256) void k_gemm4(const float* __restrict__ x,
                                               const float* __restrict__ linw,
                                               const float* __restrict__ ew2) {
    extern __shared__ float sm[];
    const float* A; int lda; const float* B; float* C;
    if (blockIdx.y == 0) {
        A = x; lda = 128; B = linw; C = g_hx;
    } else {
        int l = blockIdx.y - 1;
        A = g_S + l * DH; lda = DH * LLAY;
        B = ew2 + (size_t)l * DH * DH;
        C = g_Q + (size_t)l * NN * DH;
    }
    gemm_body(A, lda, B, C, NN, sm, blockIdx.x);
}

__global__ __launch_bounds__(256) void k_gemm(const float* __restrict__ A, int lda,
                                              const float* __restrict__ B,
                                              float* __restrict__ C, int M) {
    extern __shared__ float sm[];
    gemm_body(A, lda, B, C, M, sm, blockIdx.x);
}

// ---------- gather + aggregate + LayerNorm + ReLU (one warp per node) ----------
__global__ void k_msgln(const float* __restrict__ hx, const float* __restrict__ Q,
                        const float* __restrict__ b2, const float* __restrict__ bi,
                        const float* __restrict__ lw, const float* __restrict__ lb,
                        float* __restrict__ out) {
    int gt = blockIdx.x * blockDim.x + threadIdx.x;
    int v = gt >> 5, lane = gt & 31;
    if (v >= NN) return;
    int d0 = lane * 4;
    float a0 = 0.f, a1 = 0.f, a2 = 0.f, a3 = 0.f;
    int e0 = g_rowptr[v], e1 = g_rowptr[v + 1];
    for (int base = e0; base < e1; base += 32) {
        int idx = base + lane;
        int   rr = (idx < e1) ? g_rowS[idx] : 0;
        float ww = (idx < e1) ? g_wS[idx] : 0.f;
        int n = min(32, e1 - base);
        #pragma unroll 4
        for (int j = 0; j < n; j++) {
            int   r = __shfl_sync(0xffffffffu, rr, j);
            float w = __shfl_sync(0xffffffffu, ww, j);
            float4 hv = *(const float4*)(hx + (size_t)r * 128 + d0);
            a0 = fmaf(w, hv.x, a0);
            a1 = fmaf(w, hv.y, a1);
            a2 = fmaf(w, hv.z, a2);
            a3 = fmaf(w, hv.w, a3);
        }
    }
    float degf = (float)g_deg[v];
    float4 q  = *(const float4*)(Q + (size_t)v * 128 + d0);
    float4 c2 = *(const float4*)(b2 + d0);
    float4 cb = *(const float4*)(bi + d0);
    float x0 = a0 + q.x + degf * c2.x + cb.x;
    float x1 = a1 + q.y + degf * c2.y + cb.y;
    float x2 = a2 + q.z + degf * c2.z + cb.z;
    float x3 = a3 + q.w + degf * c2.w + cb.w;
    float s = x0 + x1 + x2 + x3;
    #pragma unroll
    for (int off = 16; off; off >>= 1) s += __shfl_xor_sync(0xffffffffu, s, off);
    float mu = s * (1.0f / 128.0f);
    float e0f = x0 - mu, e1f = x1 - mu, e2f = x2 - mu, e3f = x3 - mu;
    float vs = e0f * e0f + e1f * e1f + e2f * e2f + e3f * e3f;
    #pragma unroll
    for (int off = 16; off; off >>= 1) vs += __shfl_xor_sync(0xffffffffu, vs, off);
    float inv = rsqrtf(vs * (1.0f / 128.0f) + 1e-5f);
    float4 w4 = *(const float4*)(lw + d0);
    float4 b4 = *(const float4*)(lb + d0);
    float4 o;
    o.x = fmaxf(e0f * inv * w4.x + b4.x, 0.f);
    o.y = fmaxf(e1f * inv * w4.y + b4.y, 0.f);
    o.z = fmaxf(e2f * inv * w4.z + b4.z, 0.f);
    o.w = fmaxf(e3f * inv * w4.w + b4.w, 0.f);
    *(float4*)(out + (size_t)v * 128 + d0) = o;
}

extern "C" void kernel_launch(void* const* d_in, const int* in_sizes, int n_in,
                              void* d_out, int out_size) {
    const float* x    = (const float*)d_in[0];
    const float* ea   = (const float*)d_in[1];
    const float* linw = (const float*)d_in[2];
    const float* ew1  = (const float*)d_in[3];
    const float* eb1  = (const float*)d_in[4];
    const float* ew2  = (const float*)d_in[5];
    const float* eb2  = (const float*)d_in[6];
    const float* bias = (const float*)d_in[7];
    const float* lnw  = (const float*)d_in[8];
    const float* lnb  = (const float*)d_in[9];
    const int*   eidx = (const int*)d_in[10];
    const int* rowp = eidx;
    const int* colp = eidx + EE;
    float* out = (float*)d_out;

    cudaFuncSetAttribute(k_gemm,  cudaFuncAttributeMaxDynamicSharedMemorySize, 98304);
    cudaFuncSetAttribute(k_gemm4, cudaFuncAttributeMaxDynamicSharedMemorySize, 98304);

    float *hx, *Q, *h;
    cudaGetSymbolAddress((void**)&hx, g_hx);
    cudaGetSymbolAddress((void**)&Q,  g_Q);
    cudaGetSymbolAddress((void**)&h,  g_h);

    // CSR build (parallel 3-phase scan)
    k_zero<<<(NN + 255) / 256, 256>>>();
    k_hist<<<(EE + 255) / 256, 256>>>(colp);
    k_part<<<NBLK, 1024>>>();
    k_off<<<1, 64>>>();
    k_add<<<NBLK, 1024>>>();
    k_scatter<<<(EE + 255) / 256, 256>>>(rowp, colp, ea);

    // edge-MLP hidden + segment-sum, all 3 layers
    k_spass<<<(NN * LLAY * 32 + 255) / 256, 256>>>(ew1, eb1);

    // batched: hx0 + Q0..Q2 in one launch
    {
        dim3 grid((NN + 63) / 64, 4);
        k_gemm4<<<grid, 256, 98304>>>(x, linw, ew2);
    }

    for (int l = 0; l < LLAY; l++) {
        if (l > 0)
            k_gemm<<<(NN + 63) / 64, 256, 98304>>>(h, 128, linw + (size_t)l * 128 * 128, hx, NN);
        float* ho = (l == LLAY - 1) ? out : h;
        k_msgln<<<(NN * 32 + 255) / 256, 256>>>(hx, Q + (size_t)l * NN * DH,
                                                eb2 + l * 128, bias + l * 128,
                                                lnw + l * 128, lnb + l * 128, ho);
    }
}